// round 2
// baseline (speedup 1.0000x reference)
#include <cuda_runtime.h>

#define BATCH 131072

// Scratch (batch-innermost layouts: [feature][B])
__device__ float g_xT[256 * BATCH];   // 134 MB
__device__ float g_a1[768 * BATCH];   // 402 MB  relu(conv1)
__device__ float g_a2[192 * BATCH];   // 100 MB  relu(conv2)
__device__ float g_b1eff[768];        // H1b + pad(-1) contribution
__device__ float g_b2eff[192];        // H2b + pad(-1) contribution

// ---------------------------------------------------------------------------
// Fold the constant -1 padding into per-position biases.
// conv1: out(c,oy,ox) taps padded[2oy+ky][2ox+kx]; orig = padded-2, valid [0,16)
// conv2: same with valid range [0,8); pad contributes across all 8 in-channels.
// ---------------------------------------------------------------------------
__global__ void prep_kernel(const float* __restrict__ H1w, const float* __restrict__ H1b,
                            const float* __restrict__ H2w, const float* __restrict__ H2b) {
    int tid = threadIdx.x;
    if (tid < 768) {
        int c = tid >> 6, oy = (tid >> 3) & 7, ox = tid & 7;
        float s = 0.f;
        for (int ky = 0; ky < 5; ky++)
            for (int kx = 0; kx < 5; kx++) {
                int ir = 2 * oy + ky - 2, ic = 2 * ox + kx - 2;
                if (ir < 0 || ir >= 16 || ic < 0 || ic >= 16)
                    s += H1w[c * 25 + ky * 5 + kx];
            }
        g_b1eff[tid] = H1b[tid] - s;   // pad value is -1
    } else if (tid < 960) {
        int t = tid - 768;
        int c2 = t >> 4, oy = (t >> 2) & 3, ox = t & 3;
        float s = 0.f;
        for (int ky = 0; ky < 5; ky++)
            for (int kx = 0; kx < 5; kx++) {
                int ir = 2 * oy + ky - 2, ic = 2 * ox + kx - 2;
                if (ir < 0 || ir >= 8 || ic < 0 || ic >= 8)
                    for (int icl = 0; icl < 8; icl++)
                        s += H2w[(c2 * 8 + icl) * 25 + ky * 5 + kx];
            }
        g_b2eff[t] = H2b[t] - s;
    }
}

// ---------------------------------------------------------------------------
// Transpose x [B,256] -> xT [256,B] so batch is innermost (coalesced lanes).
// ---------------------------------------------------------------------------
__global__ void transpose_kernel(const float* __restrict__ x, int B) {
    __shared__ float tile[32][33];
    int tx = threadIdx.x, ty = threadIdx.y;
    int b0 = blockIdx.x * 32;
    int e0 = blockIdx.y * 32;
#pragma unroll
    for (int k = 0; k < 4; k++) {
        int s = ty + 8 * k;
        tile[s][tx] = x[(long long)(b0 + s) * 256 + e0 + tx];
    }
    __syncthreads();
#pragma unroll
    for (int k = 0; k < 4; k++) {
        int e = ty + 8 * k;
        g_xT[(long long)(e0 + e) * B + b0 + tx] = tile[tx][e];
    }
}

// ---------------------------------------------------------------------------
// conv1 + relu. Thread = sample. Register row window (5 rows x 20, zero-
// extended: out-of-range taps contribute 0; pad already folded into b1eff).
// ---------------------------------------------------------------------------
__global__ __launch_bounds__(256) void conv1_kernel(const float* __restrict__ H1w, int B) {
    __shared__ float w1s[300], b1s[768];
    int tid = threadIdx.x;
    for (int i = tid; i < 300; i += 256) w1s[i] = H1w[i];
    for (int i = tid; i < 768; i += 256) b1s[i] = g_b1eff[i];
    __syncthreads();
    int b = blockIdx.x * 256 + tid;
    if (b >= B) return;

    float row[5][20];
    for (int oy = 0; oy < 8; oy++) {
#pragma unroll
        for (int r = 0; r < 5; r++) {
            int orow = 2 * oy + r - 2;
            if (orow >= 0 && orow < 16) {
                row[r][0] = 0.f; row[r][1] = 0.f;
#pragma unroll
                for (int j = 0; j < 16; j++)
                    row[r][2 + j] = g_xT[(orow * 16 + j) * B + b];
                row[r][18] = 0.f; row[r][19] = 0.f;
            } else {
#pragma unroll
                for (int j = 0; j < 20; j++) row[r][j] = 0.f;
            }
        }
        for (int c = 0; c < 12; c++) {
            float w[25];
#pragma unroll
            for (int i = 0; i < 25; i++) w[i] = w1s[c * 25 + i];
            float acc[8];
#pragma unroll
            for (int ox = 0; ox < 8; ox++) acc[ox] = b1s[c * 64 + oy * 8 + ox];
#pragma unroll
            for (int r = 0; r < 5; r++)
#pragma unroll
                for (int kx = 0; kx < 5; kx++)
#pragma unroll
                    for (int ox = 0; ox < 8; ox++)
                        acc[ox] += w[r * 5 + kx] * row[r][2 * ox + kx];
#pragma unroll
            for (int ox = 0; ox < 8; ox++)
                g_a1[(c * 64 + oy * 8 + ox) * B + b] = fmaxf(acc[ox], 0.f);
        }
    }
}

// ---------------------------------------------------------------------------
// grouped conv2 + relu. Thread = sample. Groups:
//   g0: oc 0-3  <- ic 0-7      (icl = ic)
//   g1: oc 4-7  <- ic 4-11     (icl = ic-4)
//   g2: oc 8-11 <- ic {0-3,8-11} (icl = ic or ic-4)
// Two halves over oy2 so the register row window stays at 7 rows x 12.
// Redundant a1 re-reads across groups are L1-resident (~147KB reuse distance).
// ---------------------------------------------------------------------------
__global__ __launch_bounds__(128) void conv2_kernel(const float* __restrict__ H2w, int B) {
    __shared__ float w2s[2400], b2s[192];
    int tid = threadIdx.x;
    for (int i = tid; i < 2400; i += 128) w2s[i] = H2w[i];
    for (int i = tid; i < 192; i += 128) b2s[i] = g_b2eff[i];
    __syncthreads();
    int b = blockIdx.x * 128 + tid;
    if (b >= B) return;

    for (int half = 0; half < 2; half++) {
        for (int g = 0; g < 3; g++) {
            float acc[4][8];
#pragma unroll
            for (int oc4 = 0; oc4 < 4; oc4++)
#pragma unroll
                for (int l = 0; l < 2; l++)
#pragma unroll
                    for (int ox = 0; ox < 4; ox++)
                        acc[oc4][l * 4 + ox] = b2s[(g * 4 + oc4) * 16 + (2 * half + l) * 4 + ox];

            for (int icl = 0; icl < 8; icl++) {
                int ic = (g == 0) ? icl : (g == 1) ? icl + 4 : (icl < 4 ? icl : icl + 4);
                float row[7][12];
#pragma unroll
                for (int s = 0; s < 7; s++) {
                    int orow = 4 * half - 2 + s;
                    if (orow >= 0 && orow < 8) {
                        row[s][0] = 0.f; row[s][1] = 0.f;
#pragma unroll
                        for (int j = 0; j < 8; j++)
                            row[s][2 + j] = g_a1[((ic * 8 + orow) * 8 + j) * B + b];
                        row[s][10] = 0.f; row[s][11] = 0.f;
                    } else {
#pragma unroll
                        for (int j = 0; j < 12; j++) row[s][j] = 0.f;
                    }
                }
                for (int oc4 = 0; oc4 < 4; oc4++) {
                    int oc = g * 4 + oc4;
                    float w[25];
#pragma unroll
                    for (int i = 0; i < 25; i++) w[i] = w2s[(oc * 8 + icl) * 25 + i];
#pragma unroll
                    for (int l = 0; l < 2; l++)
#pragma unroll
                        for (int r = 0; r < 5; r++)
#pragma unroll
                            for (int kx = 0; kx < 5; kx++)
#pragma unroll
                                for (int ox = 0; ox < 4; ox++)
                                    acc[oc4][l * 4 + ox] += w[r * 5 + kx] * row[2 * l + r][2 * ox + kx];
                }
            }
#pragma unroll
            for (int oc4 = 0; oc4 < 4; oc4++)
#pragma unroll
                for (int l = 0; l < 2; l++)
#pragma unroll
                    for (int ox = 0; ox < 4; ox++)
                        g_a2[((g * 4 + oc4) * 16 + (2 * half + l) * 4 + ox) * B + b] =
                            fmaxf(acc[oc4][l * 4 + ox], 0.f);
        }
    }
}

// ---------------------------------------------------------------------------
// fc: relu(a2 @ H3w + H3b) @ outw + outb. Thread = sample.
// ---------------------------------------------------------------------------
__global__ __launch_bounds__(256) void fc_kernel(const float* __restrict__ H3w,
                                                 const float* __restrict__ H3b,
                                                 const float* __restrict__ outw,
                                                 const float* __restrict__ outb,
                                                 float* __restrict__ out, int B) {
    __shared__ float w3s[5760], b3s[32], w4s[300], b4s[16];
    int tid = threadIdx.x;
    for (int i = tid; i < 5760; i += 256) w3s[i] = H3w[i];
    if (tid < 30) b3s[tid] = H3b[tid];
    for (int i = tid; i < 300; i += 256) w4s[i] = outw[i];
    if (tid < 10) b4s[tid] = outb[tid];
    __syncthreads();
    int b = blockIdx.x * 256 + tid;
    if (b >= B) return;

    float h[30];
#pragma unroll
    for (int j = 0; j < 30; j++) h[j] = b3s[j];
    for (int i = 0; i < 192; i++) {
        float v = g_a2[i * B + b];
        const float2* wp = reinterpret_cast<const float2*>(w3s + i * 30);  // 8B aligned
#pragma unroll
        for (int j2 = 0; j2 < 15; j2++) {
            float2 w = wp[j2];
            h[2 * j2]     += w.x * v;
            h[2 * j2 + 1] += w.y * v;
        }
    }
    float o[10];
#pragma unroll
    for (int k = 0; k < 10; k++) o[k] = b4s[k];
#pragma unroll
    for (int j = 0; j < 30; j++) {
        float hv = fmaxf(h[j], 0.f);
#pragma unroll
        for (int k = 0; k < 10; k++)
            o[k] += w4s[j * 10 + k] * hv;
    }
#pragma unroll
    for (int k = 0; k < 10; k++)
        out[b * 10 + k] = o[k];
}

// ---------------------------------------------------------------------------
extern "C" void kernel_launch(void* const* d_in, const int* in_sizes, int n_in,
                              void* d_out, int out_size) {
    const float* x    = (const float*)d_in[0];
    const float* H1w  = (const float*)d_in[1];
    const float* H1b  = (const float*)d_in[2];
    const float* H2w  = (const float*)d_in[3];
    const float* H2b  = (const float*)d_in[4];
    const float* H3w  = (const float*)d_in[5];
    const float* H3b  = (const float*)d_in[6];
    const float* outw = (const float*)d_in[7];
    const float* outb = (const float*)d_in[8];
    float* out = (float*)d_out;

    int B = in_sizes[0] / 256;   // 131072

    prep_kernel<<<1, 1024>>>(H1w, H1b, H2w, H2b);
    transpose_kernel<<<dim3(B / 32, 8), dim3(32, 8)>>>(x, B);
    conv1_kernel<<<(B + 255) / 256, 256>>>(H1w, B);
    conv2_kernel<<<(B + 127) / 128, 128>>>(H2w, B);
    fc_kernel<<<(B + 255) / 256, 256>>>(H3w, H3b, outw, outb, out, B);
}

// round 3
// speedup vs baseline: 1.1012x; 1.1012x over previous
#include <cuda_runtime.h>

#define BATCH 131072

typedef unsigned long long u64;

// Scratch (batch-innermost layouts: [feature][B])
__device__ float g_xT[256 * BATCH];   // 134 MB
__device__ float g_a1[768 * BATCH];   // 402 MB  relu(conv1)
__device__ float g_a2[192 * BATCH];   // 100 MB  relu(conv2)
__device__ float g_b1eff[768];        // H1b + pad(-1) contribution
__device__ float g_b2eff[192];        // H2b + pad(-1) contribution

// ---------------------------------------------------------------------------
// packed f32x2 helpers (FFMA2 path — ptxas never auto-generates this)
// ---------------------------------------------------------------------------
__device__ __forceinline__ u64 ffma2(u64 a, u64 b, u64 c) {
    u64 d;
    asm("fma.rn.f32x2 %0, %1, %2, %3;" : "=l"(d) : "l"(a), "l"(b), "l"(c));
    return d;
}
__device__ __forceinline__ u64 pack2(float x) {
    u64 d; unsigned r = __float_as_uint(x);
    asm("mov.b64 %0, {%1, %1};" : "=l"(d) : "r"(r));
    return d;
}
__device__ __forceinline__ u64 pack2v(float lo, float hi) {
    u64 d; unsigned l = __float_as_uint(lo), h = __float_as_uint(hi);
    asm("mov.b64 %0, {%1, %2};" : "=l"(d) : "r"(l), "r"(h));
    return d;
}
__device__ __forceinline__ void unpack2(u64 a, float& lo, float& hi) {
    unsigned l, h;
    asm("mov.b64 {%0, %1}, %2;" : "=r"(l), "=r"(h) : "l"(a));
    lo = __uint_as_float(l); hi = __uint_as_float(h);
}
__device__ __forceinline__ u64 relu2(u64 a) {
    float lo, hi; unpack2(a, lo, hi);
    return pack2v(fmaxf(lo, 0.f), fmaxf(hi, 0.f));
}
__device__ __forceinline__ u64 ldg2(const float* p) {
    return *reinterpret_cast<const u64*>(p);
}
__device__ __forceinline__ void stg2(float* p, u64 v) {
    *reinterpret_cast<u64*>(p) = v;
}

// ---------------------------------------------------------------------------
// Fold the constant -1 padding into per-position biases.
// ---------------------------------------------------------------------------
__global__ void prep_kernel(const float* __restrict__ H1w, const float* __restrict__ H1b,
                            const float* __restrict__ H2w, const float* __restrict__ H2b) {
    int tid = threadIdx.x;
    if (tid < 768) {
        int c = tid >> 6, oy = (tid >> 3) & 7, ox = tid & 7;
        float s = 0.f;
        for (int ky = 0; ky < 5; ky++)
            for (int kx = 0; kx < 5; kx++) {
                int ir = 2 * oy + ky - 2, ic = 2 * ox + kx - 2;
                if (ir < 0 || ir >= 16 || ic < 0 || ic >= 16)
                    s += H1w[c * 25 + ky * 5 + kx];
            }
        g_b1eff[tid] = H1b[tid] - s;   // pad value is -1
    } else if (tid < 960) {
        int t = tid - 768;
        int c2 = t >> 4, oy = (t >> 2) & 3, ox = t & 3;
        float s = 0.f;
        for (int ky = 0; ky < 5; ky++)
            for (int kx = 0; kx < 5; kx++) {
                int ir = 2 * oy + ky - 2, ic = 2 * ox + kx - 2;
                if (ir < 0 || ir >= 8 || ic < 0 || ic >= 8)
                    for (int icl = 0; icl < 8; icl++)
                        s += H2w[(c2 * 8 + icl) * 25 + ky * 5 + kx];
            }
        g_b2eff[t] = H2b[t] - s;
    }
}

// ---------------------------------------------------------------------------
// Transpose x [B,256] -> xT [256,B].
// ---------------------------------------------------------------------------
__global__ void transpose_kernel(const float* __restrict__ x, int B) {
    __shared__ float tile[32][33];
    int tx = threadIdx.x, ty = threadIdx.y;
    int b0 = blockIdx.x * 32;
    int e0 = blockIdx.y * 32;
#pragma unroll
    for (int k = 0; k < 4; k++) {
        int s = ty + 8 * k;
        tile[s][tx] = x[(long long)(b0 + s) * 256 + e0 + tx];
    }
    __syncthreads();
#pragma unroll
    for (int k = 0; k < 4; k++) {
        int e = ty + 8 * k;
        g_xT[(long long)(e0 + e) * B + b0 + tx] = tile[tx][e];
    }
}

// ---------------------------------------------------------------------------
// conv1 + relu, 2 samples/thread, FFMA2.
// ox split into two halves of 4 so the register row window is 5x12 pairs.
//   half0: window cols -2..9  -> regidx = col+2  (zeros at 0,1; col>9 unused)
//   half1: window cols  6..17 -> regidx = col-6  (zeros at 10,11)
// FMA tap index for both halves: regidx = 2*ox4 + kx.
// ---------------------------------------------------------------------------
__global__ __launch_bounds__(128) void conv1_kernel(const float* __restrict__ H1w, int B) {
    __shared__ u64 w1p[300];   // (w,w) pairs
    __shared__ u64 b1p[768];
    int tid = threadIdx.x;
    for (int i = tid; i < 300; i += 128) w1p[i] = pack2(H1w[i]);
    for (int i = tid; i < 768; i += 128) b1p[i] = pack2(g_b1eff[i]);
    __syncthreads();
    int p = blockIdx.x * 128 + tid;
    int b2 = p * 2;                       // sample pair (b2, b2+1)

    u64 row[5][12];
#pragma unroll 1
    for (int half = 0; half < 2; half++) {
        for (int oy = 0; oy < 8; oy++) {
#pragma unroll
            for (int r = 0; r < 5; r++) {
                int orow = 2 * oy + r - 2;
                if (orow >= 0 && orow < 16) {
                    if (half == 0) {
                        row[r][0] = 0; row[r][1] = 0;
#pragma unroll
                        for (int j = 0; j < 10; j++)
                            row[r][2 + j] = ldg2(&g_xT[(orow * 16 + j) * B + b2]);
                    } else {
#pragma unroll
                        for (int j = 0; j < 10; j++)
                            row[r][j] = ldg2(&g_xT[(orow * 16 + 6 + j) * B + b2]);
                        row[r][10] = 0; row[r][11] = 0;
                    }
                } else {
#pragma unroll
                    for (int j = 0; j < 12; j++) row[r][j] = 0;
                }
            }
            for (int c = 0; c < 12; c++) {
                u64 acc[4];
#pragma unroll
                for (int ox = 0; ox < 4; ox++)
                    acc[ox] = b1p[c * 64 + oy * 8 + half * 4 + ox];
#pragma unroll
                for (int r = 0; r < 5; r++)
#pragma unroll
                    for (int kx = 0; kx < 5; kx++) {
                        u64 w = w1p[c * 25 + r * 5 + kx];
#pragma unroll
                        for (int ox = 0; ox < 4; ox++)
                            acc[ox] = ffma2(w, row[r][2 * ox + kx], acc[ox]);
                    }
#pragma unroll
                for (int ox = 0; ox < 4; ox++)
                    stg2(&g_a1[(c * 64 + oy * 8 + half * 4 + ox) * B + b2],
                         relu2(acc[ox]));
            }
        }
    }
}

// ---------------------------------------------------------------------------
// grouped conv2 + relu, 2 samples/thread, FFMA2. One output row at a time:
// rows window is 5x12 pairs. Groups:
//   g0: oc 0-3  <- ic 0-7 ; g1: oc 4-7 <- ic 4-11 ; g2: oc 8-11 <- ic {0-3,8-11}
// ---------------------------------------------------------------------------
__global__ __launch_bounds__(128) void conv2_kernel(const float* __restrict__ H2w, int B) {
    __shared__ u64 w2p[2400];
    __shared__ u64 b2p[192];
    int tid = threadIdx.x;
    for (int i = tid; i < 2400; i += 128) w2p[i] = pack2(H2w[i]);
    for (int i = tid; i < 192; i += 128) b2p[i] = pack2(g_b2eff[i]);
    __syncthreads();
    int p = blockIdx.x * 128 + tid;
    int b2 = p * 2;

    u64 row[5][12];
#pragma unroll 1
    for (int oy2 = 0; oy2 < 4; oy2++) {
#pragma unroll 1
        for (int g = 0; g < 3; g++) {
            u64 acc[4][4];
#pragma unroll
            for (int oc4 = 0; oc4 < 4; oc4++)
#pragma unroll
                for (int ox = 0; ox < 4; ox++)
                    acc[oc4][ox] = b2p[(g * 4 + oc4) * 16 + oy2 * 4 + ox];

            for (int icl = 0; icl < 8; icl++) {
                int ic = (g == 0) ? icl : (g == 1) ? icl + 4 : (icl < 4 ? icl : icl + 4);
#pragma unroll
                for (int r = 0; r < 5; r++) {
                    int orow = 2 * oy2 + r - 2;
                    if (orow >= 0 && orow < 8) {
                        row[r][0] = 0; row[r][1] = 0;
#pragma unroll
                        for (int j = 0; j < 8; j++)
                            row[r][2 + j] = ldg2(&g_a1[((ic * 8 + orow) * 8 + j) * B + b2]);
                        row[r][10] = 0; row[r][11] = 0;
                    } else {
#pragma unroll
                        for (int j = 0; j < 12; j++) row[r][j] = 0;
                    }
                }
                for (int oc4 = 0; oc4 < 4; oc4++) {
#pragma unroll
                    for (int r = 0; r < 5; r++)
#pragma unroll
                        for (int kx = 0; kx < 5; kx++) {
                            u64 w = w2p[((g * 4 + oc4) * 8 + icl) * 25 + r * 5 + kx];
#pragma unroll
                            for (int ox = 0; ox < 4; ox++)
                                acc[oc4][ox] = ffma2(w, row[r][2 * ox + kx], acc[oc4][ox]);
                        }
                }
            }
#pragma unroll
            for (int oc4 = 0; oc4 < 4; oc4++)
#pragma unroll
                for (int ox = 0; ox < 4; ox++)
                    stg2(&g_a2[((g * 4 + oc4) * 16 + oy2 * 4 + ox) * B + b2],
                         relu2(acc[oc4][ox]));
        }
    }
}

// ---------------------------------------------------------------------------
// fc: relu(a2 @ H3w + H3b) @ outw + outb.  2 samples/thread, FFMA2 layer 1,
// scalar tiny layer 2.
// ---------------------------------------------------------------------------
__global__ __launch_bounds__(128) void fc_kernel(const float* __restrict__ H3w,
                                                 const float* __restrict__ H3b,
                                                 const float* __restrict__ outw,
                                                 const float* __restrict__ outb,
                                                 float* __restrict__ out, int B) {
    __shared__ u64 w3p[5760];          // 46 KB (w,w) pairs
    __shared__ float w4s[300], b3s[30], b4s[10];
    int tid = threadIdx.x;
    for (int i = tid; i < 5760; i += 128) w3p[i] = pack2(H3w[i]);
    for (int i = tid; i < 300; i += 128) w4s[i] = outw[i];
    if (tid < 30) b3s[tid] = H3b[tid];
    if (tid < 10) b4s[tid] = outb[tid];
    __syncthreads();
    int p = blockIdx.x * 128 + tid;
    int b2 = p * 2;

    u64 h[30];
#pragma unroll
    for (int j = 0; j < 30; j++) h[j] = pack2(b3s[j]);
#pragma unroll 4
    for (int i = 0; i < 192; i++) {
        u64 v = ldg2(&g_a2[i * B + b2]);
#pragma unroll
        for (int j = 0; j < 30; j++)
            h[j] = ffma2(w3p[i * 30 + j], v, h[j]);
    }
    float hA[30], hB[30];
#pragma unroll
    for (int j = 0; j < 30; j++) {
        float lo, hi; unpack2(h[j], lo, hi);
        hA[j] = fmaxf(lo, 0.f); hB[j] = fmaxf(hi, 0.f);
    }
    float oA[10], oB[10];
#pragma unroll
    for (int k = 0; k < 10; k++) { oA[k] = b4s[k]; oB[k] = b4s[k]; }
#pragma unroll
    for (int j = 0; j < 30; j++)
#pragma unroll
        for (int k = 0; k < 10; k++) {
            float w = w4s[j * 10 + k];
            oA[k] += w * hA[j];
            oB[k] += w * hB[j];
        }
#pragma unroll
    for (int k = 0; k < 10; k++) {
        out[(long long)b2 * 10 + k] = oA[k];
        out[(long long)(b2 + 1) * 10 + k] = oB[k];
    }
}

// ---------------------------------------------------------------------------
extern "C" void kernel_launch(void* const* d_in, const int* in_sizes, int n_in,
                              void* d_out, int out_size) {
    const float* x    = (const float*)d_in[0];
    const float* H1w  = (const float*)d_in[1];
    const float* H1b  = (const float*)d_in[2];
    const float* H2w  = (const float*)d_in[3];
    const float* H2b  = (const float*)d_in[4];
    const float* H3w  = (const float*)d_in[5];
    const float* H3b  = (const float*)d_in[6];
    const float* outw = (const float*)d_in[7];
    const float* outb = (const float*)d_in[8];
    float* out = (float*)d_out;

    int B = in_sizes[0] / 256;   // 131072
    int P = B / 2;               // sample pairs

    prep_kernel<<<1, 1024>>>(H1w, H1b, H2w, H2b);
    transpose_kernel<<<dim3(B / 32, 8), dim3(32, 8)>>>(x, B);
    conv1_kernel<<<P / 128, 128>>>(H1w, B);
    conv2_kernel<<<P / 128, 128>>>(H2w, B);
    fc_kernel<<<P / 128, 128>>>(H3w, H3b, outw, outb, out, B);
}

// round 5
// speedup vs baseline: 1.2871x; 1.1688x over previous
#include <cuda_runtime.h>
#include <cuda_fp16.h>

#define BATCH 131072

typedef unsigned long long u64;

// Scratch (batch-innermost layouts: [feature][B])
__device__ float  g_xT[256 * BATCH];    // 134 MB fp32
__device__ __half g_a1h[768 * BATCH];   // 201 MB fp16  relu(conv1)
__device__ float  g_a2[192 * BATCH];    // 100 MB fp32  relu(conv2)
__device__ float  g_b1eff[768];
__device__ float  g_b2eff[192];

// ---------------------------------------------------------------------------
// packed f32x2 helpers (FFMA2 path — ptxas never auto-generates this)
// ---------------------------------------------------------------------------
__device__ __forceinline__ u64 ffma2(u64 a, u64 b, u64 c) {
    u64 d;
    asm("fma.rn.f32x2 %0, %1, %2, %3;" : "=l"(d) : "l"(a), "l"(b), "l"(c));
    return d;
}
__device__ __forceinline__ u64 pack2(float x) {
    u64 d; unsigned r = __float_as_uint(x);
    asm("mov.b64 %0, {%1, %1};" : "=l"(d) : "r"(r));
    return d;
}
__device__ __forceinline__ u64 pack2v(float lo, float hi) {
    u64 d; unsigned l = __float_as_uint(lo), h = __float_as_uint(hi);
    asm("mov.b64 %0, {%1, %2};" : "=l"(d) : "r"(l), "r"(h));
    return d;
}
__device__ __forceinline__ void unpack2(u64 a, float& lo, float& hi) {
    unsigned l, h;
    asm("mov.b64 {%0, %1}, %2;" : "=r"(l), "=r"(h) : "l"(a));
    lo = __uint_as_float(l); hi = __uint_as_float(h);
}
__device__ __forceinline__ u64 relu2(u64 a) {
    float lo, hi; unpack2(a, lo, hi);
    return pack2v(fmaxf(lo, 0.f), fmaxf(hi, 0.f));
}
__device__ __forceinline__ u64 ldg2(const float* p) {
    return *reinterpret_cast<const u64*>(p);
}
__device__ __forceinline__ void stg2(float* p, u64 v) {
    *reinterpret_cast<u64*>(p) = v;
}
// fp16x2 <-> f32x2
__device__ __forceinline__ unsigned f2h2(u64 v) {
    float lo, hi; unpack2(v, lo, hi);
    __half2 h = __floats2half2_rn(lo, hi);
    return *reinterpret_cast<unsigned*>(&h);
}
__device__ __forceinline__ u64 h2f2(unsigned v) {
    __half2 h = *reinterpret_cast<__half2*>(&v);
    float2 f = __half22float2(h);
    return pack2v(f.x, f.y);
}

// ---------------------------------------------------------------------------
// Fold the constant -1 padding into per-position biases.
// ---------------------------------------------------------------------------
__global__ void prep_kernel(const float* __restrict__ H1w, const float* __restrict__ H1b,
                            const float* __restrict__ H2w, const float* __restrict__ H2b) {
    int tid = threadIdx.x;
    if (tid < 768) {
        int c = tid >> 6, oy = (tid >> 3) & 7, ox = tid & 7;
        float s = 0.f;
        for (int ky = 0; ky < 5; ky++)
            for (int kx = 0; kx < 5; kx++) {
                int ir = 2 * oy + ky - 2, ic = 2 * ox + kx - 2;
                if (ir < 0 || ir >= 16 || ic < 0 || ic >= 16)
                    s += H1w[c * 25 + ky * 5 + kx];
            }
        g_b1eff[tid] = H1b[tid] - s;   // pad value is -1
    } else if (tid < 960) {
        int t = tid - 768;
        int c2 = t >> 4, oy = (t >> 2) & 3, ox = t & 3;
        float s = 0.f;
        for (int ky = 0; ky < 5; ky++)
            for (int kx = 0; kx < 5; kx++) {
                int ir = 2 * oy + ky - 2, ic = 2 * ox + kx - 2;
                if (ir < 0 || ir >= 8 || ic < 0 || ic >= 8)
                    for (int icl = 0; icl < 8; icl++)
                        s += H2w[(c2 * 8 + icl) * 25 + ky * 5 + kx];
            }
        g_b2eff[t] = H2b[t] - s;
    }
}

// ---------------------------------------------------------------------------
// Transpose x [B,256] -> xT [256,B].
// ---------------------------------------------------------------------------
__global__ void transpose_kernel(const float* __restrict__ x, int B) {
    __shared__ float tile[32][33];
    int tx = threadIdx.x, ty = threadIdx.y;
    int b0 = blockIdx.x * 32;
    int e0 = blockIdx.y * 32;
#pragma unroll
    for (int k = 0; k < 4; k++) {
        int s = ty + 8 * k;
        tile[s][tx] = x[(long long)(b0 + s) * 256 + e0 + tx];
    }
    __syncthreads();
#pragma unroll
    for (int k = 0; k < 4; k++) {
        int e = ty + 8 * k;
        g_xT[(long long)(e0 + e) * B + b0 + tx] = tile[tx][e];
    }
}

// ---------------------------------------------------------------------------
// conv1 + relu, 2 samples/thread, FFMA2, fp16 output.
// Full 16-wide row window (u64 pairs). Rows zero-filled when OOB (pad folded
// into bias); col taps outside [0,16) pruned at compile time.
// ---------------------------------------------------------------------------
__global__ __launch_bounds__(128) void conv1_kernel(const float* __restrict__ H1w, int B) {
    __shared__ u64 w1p[300];
    __shared__ u64 b1p[768];
    int tid = threadIdx.x;
    for (int i = tid; i < 300; i += 128) w1p[i] = pack2(H1w[i]);
    for (int i = tid; i < 768; i += 128) b1p[i] = pack2(g_b1eff[i]);
    __syncthreads();
    long long b2 = (long long)(blockIdx.x * 128 + tid) * 2;

    u64 row[5][16];
#pragma unroll 1
    for (int oy = 0; oy < 8; oy++) {
#pragma unroll
        for (int r = 0; r < 5; r++) {
            int orow = 2 * oy + r - 2;
            if (orow >= 0 && orow < 16) {
#pragma unroll
                for (int j = 0; j < 16; j++)
                    row[r][j] = ldg2(&g_xT[(long long)(orow * 16 + j) * B + b2]);
            } else {
#pragma unroll
                for (int j = 0; j < 16; j++) row[r][j] = 0;
            }
        }
#pragma unroll 1
        for (int c = 0; c < 12; c++) {
            u64 acc[8];
#pragma unroll
            for (int ox = 0; ox < 8; ox++)
                acc[ox] = b1p[c * 64 + oy * 8 + ox];
#pragma unroll
            for (int r = 0; r < 5; r++)
#pragma unroll
                for (int kx = 0; kx < 5; kx++) {
                    u64 w = w1p[c * 25 + r * 5 + kx];
#pragma unroll
                    for (int ox = 0; ox < 8; ox++) {
                        int col = 2 * ox + kx - 2;
                        if (col >= 0 && col < 16)
                            acc[ox] = ffma2(w, row[r][col], acc[ox]);
                    }
                }
#pragma unroll
            for (int ox = 0; ox < 8; ox++) {
                long long f = c * 64 + oy * 8 + ox;
                *reinterpret_cast<unsigned*>(&g_a1h[f * B + b2]) = f2h2(relu2(acc[ox]));
            }
        }
    }
}

// ---------------------------------------------------------------------------
// grouped conv2 + relu, 2 samples/thread, FFMA2, fp16 input.
// oy2 processed in halves {0,1} and {2,3}; per (g,icl) the needed a1 rows
// (5 for half0: orow 0..4; 6 for half1: orow 2..7) are loaded ONCE and reused
// by both oy2 of the half. OOB rows/cols are compile-time pruned (pad folded
// into b2eff). Row redundancy 1.375x, group redundancy 2x -> 2.75x total.
// ---------------------------------------------------------------------------
__global__ __launch_bounds__(128) void conv2_kernel(const float* __restrict__ H2w, int B) {
    __shared__ u64 w2p[2400];
    __shared__ u64 b2p[192];
    int tid = threadIdx.x;
    for (int i = tid; i < 2400; i += 128) w2p[i] = pack2(H2w[i]);
    for (int i = tid; i < 192; i += 128) b2p[i] = pack2(g_b2eff[i]);
    __syncthreads();
    long long b2 = (long long)(blockIdx.x * 128 + tid) * 2;

#pragma unroll
    for (int half = 0; half < 2; half++) {
        const int base  = (half == 0) ? 0 : 2;   // first loaded orow
        const int nrows = (half == 0) ? 5 : 6;
#pragma unroll 1
        for (int g = 0; g < 3; g++) {
            u64 acc[2][4][4];
#pragma unroll
            for (int l = 0; l < 2; l++)
#pragma unroll
                for (int oc4 = 0; oc4 < 4; oc4++)
#pragma unroll
                    for (int ox = 0; ox < 4; ox++)
                        acc[l][oc4][ox] =
                            b2p[(g * 4 + oc4) * 16 + (2 * half + l) * 4 + ox];

#pragma unroll 1
            for (int icl = 0; icl < 8; icl++) {
                int ic = (g == 0) ? icl : (g == 1) ? icl + 4 : (icl < 4 ? icl : icl + 4);
                u64 row[6][8];
#pragma unroll
                for (int lr = 0; lr < 6; lr++) {
                    if (lr < nrows) {
                        int orow = base + lr;
#pragma unroll
                        for (int j = 0; j < 8; j++) {
                            long long f = (ic * 8 + orow) * 8 + j;
                            unsigned raw = *reinterpret_cast<const unsigned*>(&g_a1h[f * B + b2]);
                            row[lr][j] = h2f2(raw);
                        }
                    }
                }
#pragma unroll
                for (int oc4 = 0; oc4 < 4; oc4++) {
#pragma unroll
                    for (int r = 0; r < 5; r++)
#pragma unroll
                        for (int kx = 0; kx < 5; kx++) {
                            u64 w = w2p[((g * 4 + oc4) * 8 + icl) * 25 + r * 5 + kx];
#pragma unroll
                            for (int l = 0; l < 2; l++) {
                                int oy2 = 2 * half + l;
                                int orow = 2 * oy2 + r - 2;
                                if (orow >= 0 && orow < 8) {
                                    int lr = orow - base;   // compile-time
#pragma unroll
                                    for (int ox = 0; ox < 4; ox++) {
                                        int col = 2 * ox + kx - 2;
                                        if (col >= 0 && col < 8)
                                            acc[l][oc4][ox] =
                                                ffma2(w, row[lr][col], acc[l][oc4][ox]);
                                    }
                                }
                            }
                        }
                }
            }
#pragma unroll
            for (int l = 0; l < 2; l++)
#pragma unroll
                for (int oc4 = 0; oc4 < 4; oc4++)
#pragma unroll
                    for (int ox = 0; ox < 4; ox++) {
                        long long f = (g * 4 + oc4) * 16 + (2 * half + l) * 4 + ox;
                        stg2(&g_a2[f * B + b2], relu2(acc[l][oc4][ox]));
                    }
        }
    }
}

// ---------------------------------------------------------------------------
// fc: relu(a2 @ H3w + H3b) @ outw + outb.  2 samples/thread, FFMA2 layer 1.
// ---------------------------------------------------------------------------
__global__ __launch_bounds__(128) void fc_kernel(const float* __restrict__ H3w,
                                                 const float* __restrict__ H3b,
                                                 const float* __restrict__ outw,
                                                 const float* __restrict__ outb,
                                                 float* __restrict__ out, int B) {
    __shared__ u64 w3p[5760];          // 46 KB (w,w) pairs
    __shared__ float w4s[300], b3s[30], b4s[10];
    int tid = threadIdx.x;
    for (int i = tid; i < 5760; i += 128) w3p[i] = pack2(H3w[i]);
    for (int i = tid; i < 300; i += 128) w4s[i] = outw[i];
    if (tid < 30) b3s[tid] = H3b[tid];
    if (tid < 10) b4s[tid] = outb[tid];
    __syncthreads();
    long long b2 = (long long)(blockIdx.x * 128 + tid) * 2;

    u64 h[30];
#pragma unroll
    for (int j = 0; j < 30; j++) h[j] = pack2(b3s[j]);
#pragma unroll 4
    for (int i = 0; i < 192; i++) {
        u64 v = ldg2(&g_a2[(long long)i * B + b2]);
#pragma unroll
        for (int j = 0; j < 30; j++)
            h[j] = ffma2(w3p[i * 30 + j], v, h[j]);
    }
    float hA[30], hB[30];
#pragma unroll
    for (int j = 0; j < 30; j++) {
        float lo, hi; unpack2(h[j], lo, hi);
        hA[j] = fmaxf(lo, 0.f); hB[j] = fmaxf(hi, 0.f);
    }
    float oA[10], oB[10];
#pragma unroll
    for (int k = 0; k < 10; k++) { oA[k] = b4s[k]; oB[k] = b4s[k]; }
#pragma unroll
    for (int j = 0; j < 30; j++)
#pragma unroll
        for (int k = 0; k < 10; k++) {
            float w = w4s[j * 10 + k];
            oA[k] += w * hA[j];
            oB[k] += w * hB[j];
        }
#pragma unroll
    for (int k = 0; k < 10; k++) {
        out[b2 * 10 + k]       = oA[k];
        out[(b2 + 1) * 10 + k] = oB[k];
    }
}

// ---------------------------------------------------------------------------
extern "C" void kernel_launch(void* const* d_in, const int* in_sizes, int n_in,
                              void* d_out, int out_size) {
    const float* x    = (const float*)d_in[0];
    const float* H1w  = (const float*)d_in[1];
    const float* H1b  = (const float*)d_in[2];
    const float* H2w  = (const float*)d_in[3];
    const float* H2b  = (const float*)d_in[4];
    const float* H3w  = (const float*)d_in[5];
    const float* H3b  = (const float*)d_in[6];
    const float* outw = (const float*)d_in[7];
    const float* outb = (const float*)d_in[8];
    float* out = (float*)d_out;

    int B = in_sizes[0] / 256;   // 131072
    int P = B / 2;               // sample pairs

    prep_kernel<<<1, 1024>>>(H1w, H1b, H2w, H2b);
    transpose_kernel<<<dim3(B / 32, 8), dim3(32, 8)>>>(x, B);
    conv1_kernel<<<P / 128, 128>>>(H1w, B);
    conv2_kernel<<<P / 128, 128>>>(H2w, B);
    fc_kernel<<<P / 128, 128>>>(H3w, H3b, outw, outb, out, B);
}